// round 16
// baseline (speedup 1.0000x reference)
#include <cuda_runtime.h>
#include <cuda_fp16.h>
#include <math.h>
#include <stdint.h>

#define Bv 2
#define Sv 2048
#define Dv 1024
#define Hv 16
#define HDv 64
#define HIDv 256
#define DYNv 64
#define RKv 8
#define Mv (Bv*Sv)

__device__ __forceinline__ float ex2(float x) {
    float r; asm("ex2.approx.f32 %0, %1;" : "=f"(r) : "f"(x)); return r;
}
__device__ __forceinline__ uint32_t f22h2(float x, float y) {
    __half2 h = __floats2half2_rn(x, y);
    return *reinterpret_cast<uint32_t*>(&h);
}
__device__ __forceinline__ uint32_t ex2h2(float a, float b) {
    uint32_t h = f22h2(a, b);
    uint32_t r;
    asm("ex2.approx.f16x2 %0, %1;" : "=r"(r) : "r"(h));
    return r;
}
__device__ __forceinline__ uint32_t cvta_smem(const void* p) {
    return (uint32_t)__cvta_generic_to_shared(p);
}
#define LDSM_X4(r0,r1,r2,r3, addr) \
  asm volatile("ldmatrix.sync.aligned.m8n8.x4.shared.b16 {%0,%1,%2,%3}, [%4];" \
    : "=r"(r0),"=r"(r1),"=r"(r2),"=r"(r3) : "r"(addr))
#define LDSM_X4T(r0,r1,r2,r3, addr) \
  asm volatile("ldmatrix.sync.aligned.m8n8.x4.trans.shared.b16 {%0,%1,%2,%3}, [%4];" \
    : "=r"(r0),"=r"(r1),"=r"(r2),"=r"(r3) : "r"(addr))
#define MMA_F16(d, a0,a1,a2,a3, b0, b1) \
  asm volatile("mma.sync.aligned.m16n8k16.row.col.f32.f16.f16.f32 " \
    "{%0,%1,%2,%3}, {%4,%5,%6,%7}, {%8,%9}, {%0,%1,%2,%3};" \
    : "+f"((d)[0]), "+f"((d)[1]), "+f"((d)[2]), "+f"((d)[3]) \
    : "r"(a0), "r"(a1), "r"(a2), "r"(a3), "r"(b0), "r"(b1))
#define CP16(dst, src) \
  asm volatile("cp.async.cg.shared.global [%0], [%1], 16;" :: "r"(dst), "l"(src) : "memory")
#define CP_COMMIT() asm volatile("cp.async.commit_group;" ::: "memory")
#define CP_WAIT1()  asm volatile("cp.async.wait_group 1;" ::: "memory")

// ---------------- scratch ----------------
__device__ float  g_zpart[Bv*8*Dv];
__device__ float  g_h[2*Bv*HIDv];
__device__ float  g_c[2*Bv*DYNv];
__device__ float  g_A[2*Bv*RKv*Dv];
__device__ float  g_Bm[2*Bv*Dv*RKv];
__device__ float  g_xak[Mv*RKv];
__device__ float  g_xav[Mv*RKv];
__device__ __half g_xh[Mv*Dv];
__device__ __half g_wh[4*Dv*Dv];
__device__ __half g_qf[Mv*Dv];
__device__ __half g_kf[Mv*Dv];
__device__ __half g_vf[Mv*Dv];
__device__ __half g_q16[Mv*Dv];
__device__ __half g_k16[Mv*Dv];
__device__ __half g_v16[Mv*Dv];
__device__ __half g_attnh[Mv*Dv];
__device__ float2 g_rope[Sv*32];

// ---------------- 0a) x -> fp16 ----------------
__global__ void cvt_x(const float* __restrict__ x) {
    const long i = (((long)blockIdx.y*1024 + blockIdx.x)*256 + threadIdx.x)*4;
    float4 v = *(const float4*)(x + i);
    uint2 h;
    h.x = f22h2(v.x, v.y);
    h.y = f22h2(v.z, v.w);
    *(uint2*)(g_xh + i) = h;
}

// ---------------- 0b) weights -> fp16 ----------------
__global__ void cvt_w(const float* __restrict__ Wq, const float* __restrict__ Wk,
                      const float* __restrict__ Wv, const float* __restrict__ Wo) {
    const int z = blockIdx.y;
    const long i = ((long)blockIdx.x*256 + threadIdx.x)*4;
    const float* src = z == 0 ? Wq : z == 1 ? Wk : z == 2 ? Wv : Wo;
    __half* dst = g_wh + (long)z*Dv*Dv;
    float4 v = *(const float4*)(src + i);
    uint2 h;
    h.x = f22h2(v.x, v.y);
    h.y = f22h2(v.z, v.w);
    *(uint2*)(dst + i) = h;
}

__global__ void rope_table() {
    int idx = blockIdx.x*256 + threadIdx.x;
    int s = idx >> 5, d2 = idx & 31;
    float inv = expf(-((float)d2 * (1.f/32.f)) * 9.210340371976184f);
    float ang = (float)s * inv;
    float sn, cs;
    sincosf(ang, &sn, &cs);
    g_rope[idx] = make_float2(cs, sn);
}

// ---------------- 1) pooled context partials ----------------
__global__ void pool_partial(const float* __restrict__ x) {
    int d = blockIdx.x*256 + threadIdx.x;
    int split = blockIdx.y;
    int b = blockIdx.z;
    const float* xp = x + ((long)b*Sv + split*256)*Dv + d;
    float acc = 0.f;
    #pragma unroll 8
    for (int s = 0; s < 256; s++) acc += xp[(long)s*Dv];
    g_zpart[(b*8 + split)*Dv + d] = acc;
}

// ---------------- 2a) h = silu(z @ w1 + b1) ----------------
__global__ void __launch_bounds__(256) hyp_h(
    const float* __restrict__ k_w1, const float* __restrict__ k_b1,
    const float* __restrict__ v_w1, const float* __restrict__ v_b1)
{
    __shared__ float zs[Dv];
    __shared__ float part[256];
    const int kv = blockIdx.x, b = blockIdx.y, chunk = blockIdx.z;
    const int tid = threadIdx.x;
    const float* w1 = kv ? v_w1 : k_w1;
    const float* b1 = kv ? v_b1 : k_b1;
    #pragma unroll
    for (int e = 0; e < 4; e++) {
        int d = tid*4 + e;
        float acc = 0.f;
        #pragma unroll
        for (int p = 0; p < 8; p++) acc += g_zpart[(b*8 + p)*Dv + d];
        zs[d] = acc * (1.f / (float)Sv);
    }
    __syncthreads();
    const int col = tid & 15, ks = tid >> 4;
    const int j = chunk*16 + col;
    float acc = 0.f;
    const float* wp = w1 + (long)(ks*64)*HIDv + j;
    #pragma unroll 16
    for (int dd = 0; dd < 64; dd++) acc += zs[ks*64 + dd] * wp[(long)dd*HIDv];
    part[tid] = acc;
    __syncthreads();
    if (tid < 16) {
        float a = b1[chunk*16 + tid];
        #pragma unroll
        for (int p = 0; p < 16; p++) a += part[p*16 + tid];
        float sg = 1.f / (1.f + __expf(-a));
        g_h[(kv*Bv + b)*HIDv + chunk*16 + tid] = a * sg;
    }
}

// ---------------- 2b) c = h @ w2 + b2 ----------------
__global__ void __launch_bounds__(256) hyp_c(
    const float* __restrict__ k_w2, const float* __restrict__ k_b2,
    const float* __restrict__ v_w2, const float* __restrict__ v_b2)
{
    __shared__ float hs[HIDv];
    __shared__ float part[256];
    const int kv = blockIdx.x, b = blockIdx.y, chunk = blockIdx.z;
    const int tid = threadIdx.x;
    const float* w2 = kv ? v_w2 : k_w2;
    const float* b2 = kv ? v_b2 : k_b2;
    hs[tid & 255] = g_h[(kv*Bv + b)*HIDv + (tid & 255)];
    __syncthreads();
    const int col = tid & 15, ks = tid >> 4;
    const int j = chunk*16 + col;
    float acc = 0.f;
    const float* wp = w2 + (long)(ks*16)*DYNv + j;
    #pragma unroll
    for (int i = 0; i < 16; i++) acc += hs[ks*16 + i] * wp[(long)i*DYNv];
    part[tid] = acc;
    __syncthreads();
    if (tid < 16) {
        float a = b2[chunk*16 + tid];
        #pragma unroll
        for (int p = 0; p < 16; p++) a += part[p*16 + tid];
        g_c[(kv*Bv + b)*DYNv + chunk*16 + tid] = a;
    }
}

// ---------------- 3) generators: A, Bm ----------------
__global__ void hyp_AB(const float* __restrict__ kAw, const float* __restrict__ kAb,
                       const float* __restrict__ kBw, const float* __restrict__ kBb,
                       const float* __restrict__ vAw, const float* __restrict__ vAb,
                       const float* __restrict__ vBw, const float* __restrict__ vBb) {
    __shared__ float cs[DYNv];
    int kv = blockIdx.x, b = blockIdx.y, chunk = blockIdx.z;
    if (threadIdx.x < DYNv) cs[threadIdx.x] = g_c[(kv*Bv + b)*DYNv + threadIdx.x];
    __syncthreads();
    bool isA = chunk < 32;
    int j = (isA ? chunk : chunk - 32)*256 + threadIdx.x;
    const float* w  = isA ? (kv ? vAw : kAw) : (kv ? vBw : kBw);
    const float* bb = isA ? (kv ? vAb : kAb) : (kv ? vBb : kBb);
    float acc = bb[j];
    #pragma unroll 8
    for (int t = 0; t < DYNv; t++) acc += cs[t] * w[t*(RKv*Dv) + j];
    float* dst = isA ? g_A : g_Bm;
    dst[(kv*Bv + b)*(RKv*Dv) + j] = acc;
}

// ---------------- 4) xa = x @ A^T ----------------
__global__ void __launch_bounds__(256) xa_kernel(const float* __restrict__ x) {
    const int warp = threadIdx.x >> 5, lane = threadIdx.x & 31;
    const int m = blockIdx.x*8 + warp;
    const int b = m >> 11;
    const float* xr = x + (long)m*Dv;
    const float* Ak = g_A + (long)b*(RKv*Dv);
    const float* Av = g_A + (long)(Bv + b)*(RKv*Dv);
    float acc[16];
    #pragma unroll
    for (int j = 0; j < 16; j++) acc[j] = 0.f;
    #pragma unroll
    for (int it = 0; it < 8; it++) {
        int off = (it*32 + lane)*4;
        float4 xv = *(const float4*)(xr + off);
        #pragma unroll
        for (int r = 0; r < 8; r++) {
            float4 a = *(const float4*)(Ak + r*Dv + off);
            acc[r] += xv.x*a.x + xv.y*a.y + xv.z*a.z + xv.w*a.w;
            float4 av = *(const float4*)(Av + r*Dv + off);
            acc[8+r] += xv.x*av.x + xv.y*av.y + xv.z*av.z + xv.w*av.w;
        }
    }
    #pragma unroll
    for (int j = 0; j < 16; j++) {
        #pragma unroll
        for (int o = 16; o > 0; o >>= 1)
            acc[j] += __shfl_xor_sync(0xffffffffu, acc[j], o);
    }
    if (lane == 0) {
        float4 a0 = {acc[0], acc[1], acc[2], acc[3]};
        float4 a1 = {acc[4], acc[5], acc[6], acc[7]};
        float4 v0 = {acc[8], acc[9], acc[10], acc[11]};
        float4 v1 = {acc[12], acc[13], acc[14], acc[15]};
        *(float4*)(g_xak + m*RKv)     = a0;
        *(float4*)(g_xak + m*RKv + 4) = a1;
        *(float4*)(g_xav + m*RKv)     = v0;
        *(float4*)(g_xav + m*RKv + 4) = v1;
    }
}

// ---------------- fp16 GEMM: cp.async 3-stage pipeline ----------------
#define KC 32
#define AP 40
#define BP 136
#define A_STG (128*AP)
#define B_STG (32*BP)
#define STG_H (A_STG + B_STG)
#define STAGES 3
#define GEMM_SMEM (STG_H*STAGES*2)

// ---------------- 5) fused QKV GEMM (batch-sliced via mt0) ----------------
__global__ void __launch_bounds__(256) mma_qkv(
    const float* __restrict__ bq, const float* __restrict__ bk, const float* __restrict__ bv,
    int mt0)
{
    extern __shared__ __half hsm[];
    const uint32_t sb = cvta_smem(hsm);
    const int sel = blockIdx.x >> 3;
    const int ncol = (blockIdx.x & 7) * 128;
    const __half* W   = g_wh + (long)sel*Dv*Dv;
    const float* bias = sel == 0 ? bq : sel == 1 ? bk : bv;
    __half* Dst       = sel == 0 ? g_qf : sel == 1 ? g_kf : g_vf;

    const int tid = threadIdx.x;
    const int wid = tid >> 5, lane = tid & 31;
    const int tile_m = (mt0 + blockIdx.y) * 128;
    const int wm = (wid >> 2) * 64;
    const int wn = (wid & 3) * 32;
    const int r  = lane >> 2;
    const int qd = lane & 3;
    const int lane15 = lane & 15;
    const int colSel = (lane >> 4) << 3;

    auto issue = [&](int c, int st) {
        const long k0 = (long)c*KC;
        const uint32_t aB = sb + st*(STG_H*2);
        const uint32_t bB = aB + A_STG*2;
        #pragma unroll
        for (int e = 0; e < 2; e++) {
            int id = tid + e*256;
            int ar = id >> 2, aq = id & 3;
            CP16(aB + ar*(AP*2) + aq*16,
                 (const void*)(g_xh + (long)(tile_m + ar)*Dv + k0 + aq*8));
            int br = id >> 4, bs2 = id & 15;
            CP16(bB + br*(BP*2) + bs2*16,
                 (const void*)(W + (k0 + br)*Dv + ncol + bs2*8));
        }
    };

    float acc[4][4][4];
    #pragma unroll
    for (int mi = 0; mi < 4; mi++)
        #pragma unroll
        for (int ni = 0; ni < 4; ni++)
            #pragma unroll
            for (int t = 0; t < 4; t++) acc[mi][ni][t] = 0.f;

    issue(0, 0); CP_COMMIT();
    issue(1, 1); CP_COMMIT();
    CP_WAIT1();
    __syncthreads();

    const int NCk = Dv / KC;
    for (int c = 0; c < NCk; c++) {
        const int st = c % STAGES;
        const uint32_t aBase = sb + st*(STG_H*2);
        const uint32_t bBase = aBase + A_STG*2;
        #pragma unroll
        for (int kk = 0; kk < 2; kk++) {
            uint32_t af[4][4];
            #pragma unroll
            for (int mi = 0; mi < 4; mi++)
                LDSM_X4(af[mi][0], af[mi][1], af[mi][2], af[mi][3],
                        aBase + (wm + mi*16 + lane15)*(AP*2) + (kk*16 + colSel)*2);
            uint32_t bf[2][4];
            #pragma unroll
            for (int ni2 = 0; ni2 < 2; ni2++)
                LDSM_X4T(bf[ni2][0], bf[ni2][1], bf[ni2][2], bf[ni2][3],
                         bBase + (kk*16 + lane15)*(BP*2) + (wn + ni2*16 + colSel)*2);
            #pragma unroll
            for (int mi = 0; mi < 4; mi++)
                #pragma unroll
                for (int ni = 0; ni < 4; ni++)
                    MMA_F16(acc[mi][ni], af[mi][0], af[mi][1], af[mi][2], af[mi][3],
                            bf[ni>>1][(ni&1)*2], bf[ni>>1][(ni&1)*2 + 1]);
        }
        if (c + 2 < NCk) issue(c + 2, (c + 2) % STAGES);
        CP_COMMIT();
        CP_WAIT1();
        __syncthreads();
    }

    #pragma unroll
    for (int mi = 0; mi < 4; mi++) {
        const int row0 = tile_m + wm + mi*16 + r;
        const int b0 = row0 >> 11, s0 = row0 & 2047;
        #pragma unroll
        for (int ni = 0; ni < 4; ni++) {
            const int col = ncol + wn + ni*8 + 2*qd;
            const float bx = __ldg(bias + col), by = __ldg(bias + col + 1);
            long d0 = ((long)(b0*Hv + (col >> 6))*Sv + s0)*HDv + (col & 63);
            *(__half2*)(Dst + d0)         = __floats2half2_rn(acc[mi][ni][0] + bx, acc[mi][ni][1] + by);
            *(__half2*)(Dst + d0 + 8*HDv) = __floats2half2_rn(acc[mi][ni][2] + bx, acc[mi][ni][3] + by);
        }
    }
}

// ---------------- 6) output projection GEMM (m-sliced via mt0) ----------------
__global__ void __launch_bounds__(256) mma_out(
    const float* __restrict__ bias, float* __restrict__ C, int mt0)
{
    extern __shared__ __half hsm[];
    const uint32_t sb = cvta_smem(hsm);
    const __half* W = g_wh + 3L*Dv*Dv;
    const int tid = threadIdx.x;
    const int wid = tid >> 5, lane = tid & 31;
    const int tile_m = (mt0 + blockIdx.y) * 128;
    const int tile_n = blockIdx.x * 128;
    const int wm = (wid >> 2) * 64;
    const int wn = (wid & 3) * 32;
    const int r  = lane >> 2;
    const int qd = lane & 3;
    const int lane15 = lane & 15;
    const int colSel = (lane >> 4) << 3;

    auto issue = [&](int c, int st) {
        const long k0 = (long)c*KC;
        const uint32_t aB = sb + st*(STG_H*2);
        const uint32_t bB = aB + A_STG*2;
        #pragma unroll
        for (int e = 0; e < 2; e++) {
            int id = tid + e*256;
            int ar = id >> 2, aq = id & 3;
            CP16(aB + ar*(AP*2) + aq*16,
                 (const void*)(g_attnh + (long)(tile_m + ar)*Dv + k0 + aq*8));
            int br = id >> 4, bs2 = id & 15;
            CP16(bB + br*(BP*2) + bs2*16,
                 (const void*)(W + (k0 + br)*Dv + tile_n + bs2*8));
        }
    };

    float acc[4][4][4];
    #pragma unroll
    for (int mi = 0; mi < 4; mi++)
        #pragma unroll
        for (int ni = 0; ni < 4; ni++)
            #pragma unroll
            for (int t = 0; t < 4; t++) acc[mi][ni][t] = 0.f;

    issue(0, 0); CP_COMMIT();
    issue(1, 1); CP_COMMIT();
    CP_WAIT1();
    __syncthreads();

    const int NCk = Dv / KC;
    for (int c = 0; c < NCk; c++) {
        const int st = c % STAGES;
        const uint32_t aBase = sb + st*(STG_H*2);
        const uint32_t bBase = aBase + A_STG*2;
        #pragma unroll
        for (int kk = 0; kk < 2; kk++) {
            uint32_t af[4][4];
            #pragma unroll
            for (int mi = 0; mi < 4; mi++)
                LDSM_X4(af[mi][0], af[mi][1], af[mi][2], af[mi][3],
                        aBase + (wm + mi*16 + lane15)*(AP*2) + (kk*16 + colSel)*2);
            uint32_t bf[2][4];
            #pragma unroll
            for (int ni2 = 0; ni2 < 2; ni2++)
                LDSM_X4T(bf[ni2][0], bf[ni2][1], bf[ni2][2], bf[ni2][3],
                         bBase + (kk*16 + lane15)*(BP*2) + (wn + ni2*16 + colSel)*2);
            #pragma unroll
            for (int mi = 0; mi < 4; mi++)
                #pragma unroll
                for (int ni = 0; ni < 4; ni++)
                    MMA_F16(acc[mi][ni], af[mi][0], af[mi][1], af[mi][2], af[mi][3],
                            bf[ni>>1][(ni&1)*2], bf[ni>>1][(ni&1)*2 + 1]);
        }
        if (c + 2 < NCk) issue(c + 2, (c + 2) % STAGES);
        CP_COMMIT();
        CP_WAIT1();
        __syncthreads();
    }

    #pragma unroll
    for (int mi = 0; mi < 4; mi++) {
        const int row0 = tile_m + wm + mi*16 + r;
        #pragma unroll
        for (int ni = 0; ni < 4; ni++) {
            const int col = tile_n + wn + ni*8 + 2*qd;
            const float bx = __ldg(bias + col), by = __ldg(bias + col + 1);
            float2 v0, v1;
            v0.x = acc[mi][ni][0] + bx; v0.y = acc[mi][ni][1] + by;
            v1.x = acc[mi][ni][2] + bx; v1.y = acc[mi][ni][3] + by;
            *(float2*)(C + (long)row0*Dv + col)     = v0;
            *(float2*)(C + (long)(row0+8)*Dv + col) = v1;
        }
    }
}

// ---------------- 7) rope + dyn correction (single batch) ----------------
__device__ __forceinline__ float dot8(const float* a, const float* bp) {
    float4 a0 = *(const float4*)a,  a1 = *(const float4*)(a + 4);
    float4 b0 = *(const float4*)bp, b1 = *(const float4*)(bp + 4);
    return a0.x*b0.x + a0.y*b0.y + a0.z*b0.z + a0.w*b0.w
         + a1.x*b1.x + a1.y*b1.y + a1.z*b1.z + a1.w*b1.w;
}

__global__ void rope_dyn(int b) {
    int idx = blockIdx.x*256 + threadIdx.x;
    int d2 = idx & 31;
    int s  = (idx >> 5) & 2047;
    int h  = (idx >> 16) & 15;
    long base = ((long)((b*Hv + h)*Sv + s))*HDv;
    int m = b*Sv + s;
    const float* xak = g_xak + (long)m*RKv;
    const float* xav = g_xav + (long)m*RKv;
    const float* Bmk = g_Bm + (long)b*(Dv*RKv);
    const float* Bmv = g_Bm + (long)(Bv + b)*(Dv*RKv);
    int c0 = h*HDv + d2;
    float dk0 = 0.125f * dot8(xak, Bmk + c0*RKv);
    float dk1 = 0.125f * dot8(xak, Bmk + (c0+32)*RKv);
    float dv0 = 0.125f * dot8(xav, Bmv + c0*RKv);
    float dv1 = 0.125f * dot8(xav, Bmv + (c0+32)*RKv);

    float2 t = g_rope[(s << 5) | d2];
    float cs = t.x, sn = t.y;

    float q0 = __half2float(g_qf[base + d2]), q1 = __half2float(g_qf[base + d2 + 32]);
    g_q16[base + d2]      = __float2half(q0*cs - q1*sn);
    g_q16[base + d2 + 32] = __float2half(q1*cs + q0*sn);
    float k0 = __half2float(g_kf[base + d2]) + dk0;
    float k1 = __half2float(g_kf[base + d2 + 32]) + dk1;
    g_k16[base + d2]      = __float2half(k0*cs - k1*sn);
    g_k16[base + d2 + 32] = __float2half(k1*cs + k0*sn);
    g_v16[base + d2]      = __float2half(__half2float(g_vf[base + d2]) + dv0);
    g_v16[base + d2 + 32] = __float2half(__half2float(g_vf[base + d2 + 32]) + dv1);
}

// ---------------- 8) causal flash attention (batch-sliced via bh0) ----------------
#define FQP 72
#define FKP 72
#define KTILE_B (64*FKP*2)
#define KVSTR   (2*KTILE_B)
#define FLASH_SMEM (64*FQP*2 + 2*KVSTR)
#define FSCL 0.18033688011112042f

__global__ void __launch_bounds__(128) flash_mma(int bh0)
{
    extern __shared__ __half hsm[];
    __half* Qs = hsm;
    const uint32_t qBase  = cvta_smem(Qs);
    const uint32_t kv0Base = qBase + 64*FQP*2;

    const int qt = 31 - blockIdx.x;
    const int bh = bh0 + blockIdx.y;
    const int tid = threadIdx.x;
    const int warp = tid >> 5, lane = tid & 31;
    const int g = lane >> 2, tig = lane & 3;
    const int r0 = warp*16 + g;
    const int lane15 = lane & 15;
    const int colSel = (lane >> 4) << 3;
    const int krow_off = (lane & 7) + ((lane >> 4) & 1)*8;
    const int kcol_off = ((lane >> 3) & 1)*8;
    const int vrow_off = (lane & 7) + ((lane >> 3) & 1)*8;
    const int vcol_off = ((lane >> 4) & 1)*8;

    const __half* Qb = g_q16 + ((long)bh*Sv + qt*64)*HDv;
    const __half* Kb = g_k16 + (long)bh*Sv*HDv;
    const __half* Vb = g_v16 + (long)bh*Sv*HDv;

    const int lrow = tid >> 4;
    const int lcol = (tid & 15) * 4;

    #pragma unroll
    for (int it = 0; it < 8; it++) {
        int rr = lrow + it*8;
        *(uint2*)(Qs + rr*FQP + lcol) = *(const uint2*)(Qb + rr*HDv + lcol);
    }
    __syncthreads();
    uint32_t qf[4][4];
    #pragma unroll
    for (int kk = 0; kk < 4; kk++)
        LDSM_X4(qf[kk][0], qf[kk][1], qf[kk][2], qf[kk][3],
                qBase + (warp*16 + lane15)*(FQP*2) + (kk*16 + colSel)*2);

    float oa[8][4];
    #pragma unroll
    for (int nt = 0; nt < 8; nt++)
        #pragma unroll
        for (int e = 0; e < 4; e++) oa[nt][e] = 0.f;
    float m0 = -1e30f, m1 = -1e30f, l0 = 0.f, l1 = 0.f;

    uint2 kR[8], vR[8];
    #pragma unroll
    for (int it = 0; it < 8; it++) {
        int rr = lrow + it*8;
        kR[it] = *(const uint2*)(Kb + ((long)rr)*HDv + lcol);
        vR[it] = *(const uint2*)(Vb + ((long)rr)*HDv + lcol);
    }

    for (int jt = 0; jt <= qt; jt++) {
        const uint32_t kB = kv0Base + (jt & 1)*KVSTR;
        const uint32_t vB = kB + KTILE_B;
        __half* KsW = (__half*)(hsm + (kB - qBase)/2);
        __half* VsW = KsW + 64*FKP;
        #pragma unroll
        for (int it = 0; it < 8; it++) {
            int rr = lrow + it*8;
            *(uint2*)(KsW + rr*FKP + lcol) = kR[it];
            *(uint2*)(VsW + rr*FKP + lcol) = vR[it];
        }
        __syncthreads();
        if (jt < qt) {
            #pragma unroll
            for (int it = 0; it < 8; it++) {
                int rr = (jt + 1)*64 + lrow + it*8;
                kR[it] = *(const uint2*)(Kb + ((long)rr)*HDv + lcol);
                vR[it] = *(const uint2*)(Vb + ((long)rr)*HDv + lcol);
            }
        }

        float s[8][4];
        #pragma unroll
        for (int nt = 0; nt < 8; nt++)
            #pragma unroll
            for (int e = 0; e < 4; e++) s[nt][e] = 0.f;
        #pragma unroll
        for (int ni2 = 0; ni2 < 4; ni2++) {
            #pragma unroll
            for (int kk = 0; kk < 4; kk++) {
                uint32_t kf0, kf1, kf2, kf3;
                LDSM_X4(kf0, kf1, kf2, kf3,
                        kB + (ni2*16 + krow_off)*(FKP*2) + (kk*16 + kcol_off)*2);
                MMA_F16(s[2*ni2],   qf[kk][0], qf[kk][1], qf[kk][2], qf[kk][3], kf0, kf1);
                MMA_F16(s[2*ni2+1], qf[kk][0], qf[kk][1], qf[kk][2], qf[kk][3], kf2, kf3);
            }
        }

        #pragma unroll
        for (int nt = 0; nt < 8; nt++) {
            #pragma unroll
            for (int e = 0; e < 4; e++) s[nt][e] *= FSCL;
            if (jt == qt) {
                int c0 = nt*8 + 2*tig;
                if (c0     > r0)     s[nt][0] = -1e30f;
                if (c0 + 1 > r0)     s[nt][1] = -1e30f;
                if (c0     > r0 + 8) s[nt][2] = -1e30f;
                if (c0 + 1 > r0 + 8) s[nt][3] = -1e30f;
            }
        }

        float mx0 = -1e30f, mx1 = -1e30f;
        #pragma unroll
        for (int nt = 0; nt < 8; nt++) {
            mx0 = fmaxf(mx0, fmaxf(s[nt][0], s[nt][1]));
            mx1 = fmaxf(mx1, fmaxf(s[nt][2], s[nt][3]));
        }
        mx0 = fmaxf(mx0, __shfl_xor_sync(0xffffffffu, mx0, 1));
        mx0 = fmaxf(mx0, __shfl_xor_sync(0xffffffffu, mx0, 2));
        mx1 = fmaxf(mx1, __shfl_xor_sync(0xffffffffu, mx1, 1));
        mx1 = fmaxf(mx1, __shfl_xor_sync(0xffffffffu, mx1, 2));
        float mn0 = fmaxf(m0, mx0), mn1 = fmaxf(m1, mx1);
        float al0 = ex2(m0 - mn0), al1 = ex2(m1 - mn1);
        m0 = mn0; m1 = mn1;

        uint32_t ph0[8], ph1[8];
        float ls0 = 0.f, ls1 = 0.f;
        #pragma unroll
        for (int nt = 0; nt < 8; nt++) {
            ph0[nt] = ex2h2(s[nt][0] - m0, s[nt][1] - m0);
            ph1[nt] = ex2h2(s[nt][2] - m1, s[nt][3] - m1);
            float2 fa = __half22float2(*(__half2*)&ph0[nt]);
            float2 fb = __half22float2(*(__half2*)&ph1[nt]);
            ls0 += fa.x + fa.y;
            ls1 += fb.x + fb.y;
        }
        ls0 += __shfl_xor_sync(0xffffffffu, ls0, 1);
        ls0 += __shfl_xor_sync(0xffffffffu, ls0, 2);
        ls1 += __shfl_xor_sync(0xffffffffu, ls1, 1);
        ls1 += __shfl_xor_sync(0xffffffffu, ls1, 2);
        l0 = l0*al0 + ls0;
        l1 = l1*al1 + ls1;
        #pragma unroll
        for (int nt = 0; nt < 8; nt++) {
            oa[nt][0] *= al0; oa[nt][1] *= al0;
            oa[nt][2] *= al1; oa[nt][3] *= al1;
        }

        #pragma unroll
        for (int kt = 0; kt < 4; kt++) {
            uint32_t pa0 = ph0[2*kt];
            uint32_t pa1 = ph1[2*kt];
            uint32_t pa2 = ph0[2*kt+1];
            uint32_t pa3 = ph1[2*kt+1];
            #pragma unroll
            for (int g16 = 0; g16 < 4; g16++) {
                uint32_t vf0, vf1, vf2, vf3;
                LDSM_X4T(vf0, vf1, vf2, vf3,
                         vB + (kt*16 + vrow_off)*(FKP*2) + (g16*16 + vcol_off)*2);
                MMA_F16(oa[2*g16],   pa0, pa1, pa2, pa3, vf0, vf1);
                MMA_F16(oa[2*g16+1], pa0, pa1, pa2, pa3, vf2, vf3);
            }
        }
    }

    const int b = bh >> 4, h = bh & 15;
    const float inv0 = 1.f / l0, inv1 = 1.f / l1;
    const int rg0 = qt*64 + r0;
    #pragma unroll
    for (int nt = 0; nt < 8; nt++) {
        int col = h*HDv + nt*8 + 2*tig;
        __half2* o0 = (__half2*)(g_attnh + ((long)(b*Sv + rg0))*Dv + col);
        __half2* o1 = (__half2*)(g_attnh + ((long)(b*Sv + rg0 + 8))*Dv + col);
        *o0 = __floats2half2_rn(oa[nt][0]*inv0, oa[nt][1]*inv0);
        *o1 = __floats2half2_rn(oa[nt][2]*inv1, oa[nt][3]*inv1);
    }
}

// ---------------- launch: R14 topology (2 streams) + split cvt ----------------
extern "C" void kernel_launch(void* const* d_in, const int* in_sizes, int n_in,
                              void* d_out, int out_size) {
    const float* x      = (const float*)d_in[0];
    const float* Wq     = (const float*)d_in[1];
    const float* bq     = (const float*)d_in[2];
    const float* Wo     = (const float*)d_in[3];
    const float* bo     = (const float*)d_in[4];
    const float* Wk     = (const float*)d_in[5];
    const float* bk     = (const float*)d_in[6];
    const float* k_w1   = (const float*)d_in[7];
    const float* k_b1   = (const float*)d_in[8];
    const float* k_w2   = (const float*)d_in[9];
    const float* k_b2   = (const float*)d_in[10];
    const float* k_gA_w = (const float*)d_in[11];
    const float* k_gA_b = (const float*)d_in[12];
    const float* k_gB_w = (const float*)d_in[13];
    const float* k_gB_b = (const float*)d_in[14];
    const float* Wv     = (const float*)d_in[15];
    const float* bv     = (const float*)d_in[16];
    const float* v_w1   = (const float*)d_in[17];
    const float* v_b1   = (const float*)d_in[18];
    const float* v_w2   = (const float*)d_in[19];
    const float* v_b2   = (const float*)d_in[20];
    const float* v_gA_w = (const float*)d_in[21];
    const float* v_gA_b = (const float*)d_in[22];
    const float* v_gB_w = (const float*)d_in[23];
    const float* v_gB_b = (const float*)d_in[24];
    float* out = (float*)d_out;

    cudaFuncSetAttribute(flash_mma, cudaFuncAttributeMaxDynamicSharedMemorySize, FLASH_SMEM);
    cudaFuncSetAttribute(mma_qkv, cudaFuncAttributeMaxDynamicSharedMemorySize, GEMM_SMEM);
    cudaFuncSetAttribute(mma_out, cudaFuncAttributeMaxDynamicSharedMemorySize, GEMM_SMEM);

    static cudaStream_t s1 = nullptr, s2 = nullptr;
    static cudaEvent_t evFork = nullptr, evW = nullptr, evP = nullptr, evQ0 = nullptr, evJ2 = nullptr;
    if (s1 == nullptr) {
        cudaStreamCreateWithFlags(&s1, cudaStreamNonBlocking);
        cudaStreamCreateWithFlags(&s2, cudaStreamNonBlocking);
        cudaEventCreateWithFlags(&evFork, cudaEventDisableTiming);
        cudaEventCreateWithFlags(&evW,    cudaEventDisableTiming);
        cudaEventCreateWithFlags(&evP,    cudaEventDisableTiming);
        cudaEventCreateWithFlags(&evQ0,   cudaEventDisableTiming);
        cudaEventCreateWithFlags(&evJ2,   cudaEventDisableTiming);
    }

    // s1: weight cvt first (gates qkv), then prologue chain
    cudaEventRecord(evFork, 0);
    cudaStreamWaitEvent(s1, evFork, 0);
    cvt_w<<<dim3(1024, 4), 256, 0, s1>>>(Wq, Wk, Wv, Wo);
    cudaEventRecord(evW, s1);
    rope_table<<<256, 256, 0, s1>>>();
    pool_partial<<<dim3(4, 8, Bv), 256, 0, s1>>>(x);
    hyp_h<<<dim3(2, Bv, 16), 256, 0, s1>>>(k_w1, k_b1, v_w1, v_b1);
    hyp_c<<<dim3(2, Bv, 4), 256, 0, s1>>>(k_w2, k_b2, v_w2, v_b2);
    hyp_AB<<<dim3(2, Bv, 64), 256, 0, s1>>>(k_gA_w, k_gA_b, k_gB_w, k_gB_b,
                                            v_gA_w, v_gA_b, v_gB_w, v_gB_b);
    xa_kernel<<<512, 256, 0, s1>>>(x);
    cudaEventRecord(evP, s1);

    // main: cvt_x -> qkv b0 -> qkv b1
    cvt_x<<<dim3(1024, 4), 256>>>(x);
    cudaStreamWaitEvent(0, evW, 0);
    mma_qkv<<<dim3(24, 16), 256, GEMM_SMEM>>>(bq, bk, bv, 0);
    cudaEventRecord(evQ0, 0);
    mma_qkv<<<dim3(24, 16), 256, GEMM_SMEM>>>(bq, bk, bv, 16);

    // s2: batch-0 tail pipeline (overlaps qkv b1 / flash b1)
    cudaStreamWaitEvent(s2, evQ0, 0);
    cudaStreamWaitEvent(s2, evP, 0);
    rope_dyn<<<4096, 256, 0, s2>>>(0);
    flash_mma<<<dim3(32, 16), 128, FLASH_SMEM, s2>>>(0);
    mma_out<<<dim3(8, 16), 256, GEMM_SMEM, s2>>>(bo, out, 0);
    cudaEventRecord(evJ2, s2);

    // main: batch-1 tail pipeline
    cudaStreamWaitEvent(0, evP, 0);
    rope_dyn<<<4096, 256>>>(1);
    flash_mma<<<dim3(32, 16), 128, FLASH_SMEM>>>(16);
    mma_out<<<dim3(8, 16), 256, GEMM_SMEM>>>(bo, out, 16);
    cudaStreamWaitEvent(0, evJ2, 0);
}

// round 17
// speedup vs baseline: 1.0330x; 1.0330x over previous
#include <cuda_runtime.h>
#include <cuda_fp16.h>
#include <math.h>
#include <stdint.h>

#define Bv 2
#define Sv 2048
#define Dv 1024
#define Hv 16
#define HDv 64
#define HIDv 256
#define DYNv 64
#define RKv 8
#define Mv (Bv*Sv)

__device__ __forceinline__ float ex2(float x) {
    float r; asm("ex2.approx.f32 %0, %1;" : "=f"(r) : "f"(x)); return r;
}
__device__ __forceinline__ uint32_t f22h2(float x, float y) {
    __half2 h = __floats2half2_rn(x, y);
    return *reinterpret_cast<uint32_t*>(&h);
}
__device__ __forceinline__ uint32_t ex2h2(float a, float b) {
    uint32_t h = f22h2(a, b);
    uint32_t r;
    asm("ex2.approx.f16x2 %0, %1;" : "=r"(r) : "r"(h));
    return r;
}
__device__ __forceinline__ uint32_t cvta_smem(const void* p) {
    return (uint32_t)__cvta_generic_to_shared(p);
}
#define LDSM_X4(r0,r1,r2,r3, addr) \
  asm volatile("ldmatrix.sync.aligned.m8n8.x4.shared.b16 {%0,%1,%2,%3}, [%4];" \
    : "=r"(r0),"=r"(r1),"=r"(r2),"=r"(r3) : "r"(addr))
#define LDSM_X4T(r0,r1,r2,r3, addr) \
  asm volatile("ldmatrix.sync.aligned.m8n8.x4.trans.shared.b16 {%0,%1,%2,%3}, [%4];" \
    : "=r"(r0),"=r"(r1),"=r"(r2),"=r"(r3) : "r"(addr))
#define MMA_F16(d, a0,a1,a2,a3, b0, b1) \
  asm volatile("mma.sync.aligned.m16n8k16.row.col.f32.f16.f16.f32 " \
    "{%0,%1,%2,%3}, {%4,%5,%6,%7}, {%8,%9}, {%0,%1,%2,%3};" \
    : "+f"((d)[0]), "+f"((d)[1]), "+f"((d)[2]), "+f"((d)[3]) \
    : "r"(a0), "r"(a1), "r"(a2), "r"(a3), "r"(b0), "r"(b1))
#define CP16(dst, src) \
  asm volatile("cp.async.cg.shared.global [%0], [%1], 16;" :: "r"(dst), "l"(src) : "memory")
#define CP_COMMIT() asm volatile("cp.async.commit_group;" ::: "memory")
#define CP_WAIT1()  asm volatile("cp.async.wait_group 1;" ::: "memory")

// ---------------- scratch ----------------
__device__ float  g_zpart[Bv*8*Dv];
__device__ float  g_hpart[2*Bv*16*HIDv];
__device__ float  g_c[2*Bv*DYNv];
__device__ float  g_A[2*Bv*RKv*Dv];
__device__ float  g_Bm[2*Bv*Dv*RKv];
__device__ float  g_xak[Mv*RKv];
__device__ float  g_xav[Mv*RKv];
__device__ __half g_xh[Mv*Dv];
__device__ __half g_wh[4*Dv*Dv];
__device__ __half g_qf[Mv*Dv];
__device__ __half g_kf[Mv*Dv];
__device__ __half g_vf[Mv*Dv];
__device__ __half g_q16[Mv*Dv];
__device__ __half g_k16[Mv*Dv];
__device__ __half g_v16[Mv*Dv];
__device__ __half g_attnh[Mv*Dv];
__device__ float2 g_rope[Sv*32];

// ---------------- 0a) x -> fp16 ----------------
__global__ void cvt_x(const float* __restrict__ x) {
    const long i = (((long)blockIdx.y*1024 + blockIdx.x)*256 + threadIdx.x)*4;
    float4 v = *(const float4*)(x + i);
    uint2 h;
    h.x = f22h2(v.x, v.y);
    h.y = f22h2(v.z, v.w);
    *(uint2*)(g_xh + i) = h;
}

// ---------------- 0b) weights -> fp16 ----------------
__global__ void cvt_w(const float* __restrict__ Wq, const float* __restrict__ Wk,
                      const float* __restrict__ Wv, const float* __restrict__ Wo) {
    const int z = blockIdx.y;
    const long i = ((long)blockIdx.x*256 + threadIdx.x)*4;
    const float* src = z == 0 ? Wq : z == 1 ? Wk : z == 2 ? Wv : Wo;
    __half* dst = g_wh + (long)z*Dv*Dv;
    float4 v = *(const float4*)(src + i);
    uint2 h;
    h.x = f22h2(v.x, v.y);
    h.y = f22h2(v.z, v.w);
    *(uint2*)(dst + i) = h;
}

__global__ void rope_table() {
    int idx = blockIdx.x*256 + threadIdx.x;
    int s = idx >> 5, d2 = idx & 31;
    float inv = expf(-((float)d2 * (1.f/32.f)) * 9.210340371976184f);
    float ang = (float)s * inv;
    float sn, cs;
    sincosf(ang, &sn, &cs);
    g_rope[idx] = make_float2(cs, sn);
}

// ---------------- 1) pooled context partials ----------------
__global__ void pool_partial(const float* __restrict__ x) {
    int d = blockIdx.x*256 + threadIdx.x;
    int split = blockIdx.y;
    int b = blockIdx.z;
    const float* xp = x + ((long)b*Sv + split*256)*Dv + d;
    float acc = 0.f;
    #pragma unroll 8
    for (int s = 0; s < 256; s++) acc += xp[(long)s*Dv];
    g_zpart[(b*8 + split)*Dv + d] = acc;
}

// ---------------- 2a) h partials: slab ks2 of z @ w1 (coalesced) ----------------
__global__ void __launch_bounds__(256) hyp_h(
    const float* __restrict__ k_w1, const float* __restrict__ v_w1)
{
    __shared__ float zs[64];
    const int kv = blockIdx.x, b = blockIdx.y, ks2 = blockIdx.z;  // ks2 0..15
    const int tid = threadIdx.x;
    const float* w1 = kv ? v_w1 : k_w1;
    if (tid < 64) {
        int d = ks2*64 + tid;
        float acc = 0.f;
        #pragma unroll
        for (int p = 0; p < 8; p++) acc += g_zpart[(b*8 + p)*Dv + d];
        zs[tid] = acc * (1.f / (float)Sv);
    }
    __syncthreads();
    float acc = 0.f;
    const float* wp = w1 + (long)(ks2*64)*HIDv + tid;
    #pragma unroll 16
    for (int dd = 0; dd < 64; dd++) acc += zs[dd] * wp[(long)dd*HIDv];
    g_hpart[((kv*Bv + b)*16 + ks2)*HIDv + tid] = acc;
}

// ---------------- 2b) combine h (bias+silu) + c = h @ w2 + b2 ----------------
__global__ void __launch_bounds__(256) hyp_c(
    const float* __restrict__ k_w2, const float* __restrict__ k_b2,
    const float* __restrict__ v_w2, const float* __restrict__ v_b2,
    const float* __restrict__ k_b1, const float* __restrict__ v_b1)
{
    __shared__ float hs[HIDv];
    __shared__ float part[256];
    const int kv = blockIdx.x, b = blockIdx.y, chunk = blockIdx.z;
    const int tid = threadIdx.x;
    const float* w2 = kv ? v_w2 : k_w2;
    const float* b2 = kv ? v_b2 : k_b2;
    const float* b1 = kv ? v_b1 : k_b1;
    {
        float a = b1[tid];
        const float* hp = g_hpart + (long)(kv*Bv + b)*16*HIDv + tid;
        #pragma unroll
        for (int p = 0; p < 16; p++) a += hp[p*HIDv];
        float sg = 1.f / (1.f + __expf(-a));
        hs[tid] = a * sg;
    }
    __syncthreads();
    const int col = tid & 15, ks = tid >> 4;
    const int j = chunk*16 + col;
    float acc = 0.f;
    const float* wp = w2 + (long)(ks*16)*DYNv + j;
    #pragma unroll
    for (int i = 0; i < 16; i++) acc += hs[ks*16 + i] * wp[(long)i*DYNv];
    part[tid] = acc;
    __syncthreads();
    if (tid < 16) {
        float a = b2[chunk*16 + tid];
        #pragma unroll
        for (int p = 0; p < 16; p++) a += part[p*16 + tid];
        g_c[(kv*Bv + b)*DYNv + chunk*16 + tid] = a;
    }
}

// ---------------- 3) generators: A, Bm ----------------
__global__ void hyp_AB(const float* __restrict__ kAw, const float* __restrict__ kAb,
                       const float* __restrict__ kBw, const float* __restrict__ kBb,
                       const float* __restrict__ vAw, const float* __restrict__ vAb,
                       const float* __restrict__ vBw, const float* __restrict__ vBb) {
    __shared__ float cs[DYNv];
    int kv = blockIdx.x, b = blockIdx.y, chunk = blockIdx.z;
    if (threadIdx.x < DYNv) cs[threadIdx.x] = g_c[(kv*Bv + b)*DYNv + threadIdx.x];
    __syncthreads();
    bool isA = chunk < 32;
    int j = (isA ? chunk : chunk - 32)*256 + threadIdx.x;
    const float* w  = isA ? (kv ? vAw : kAw) : (kv ? vBw : kBw);
    const float* bb = isA ? (kv ? vAb : kAb) : (kv ? vBb : kBb);
    float acc = bb[j];
    #pragma unroll 8
    for (int t = 0; t < DYNv; t++) acc += cs[t] * w[t*(RKv*Dv) + j];
    float* dst = isA ? g_A : g_Bm;
    dst[(kv*Bv + b)*(RKv*Dv) + j] = acc;
}

// ---------------- 4) xa = x @ A^T ----------------
__global__ void __launch_bounds__(256) xa_kernel(const float* __restrict__ x) {
    const int warp = threadIdx.x >> 5, lane = threadIdx.x & 31;
    const int m = blockIdx.x*8 + warp;
    const int b = m >> 11;
    const float* xr = x + (long)m*Dv;
    const float* Ak = g_A + (long)b*(RKv*Dv);
    const float* Av = g_A + (long)(Bv + b)*(RKv*Dv);
    float acc[16];
    #pragma unroll
    for (int j = 0; j < 16; j++) acc[j] = 0.f;
    #pragma unroll
    for (int it = 0; it < 8; it++) {
        int off = (it*32 + lane)*4;
        float4 xv = *(const float4*)(xr + off);
        #pragma unroll
        for (int r = 0; r < 8; r++) {
            float4 a = *(const float4*)(Ak + r*Dv + off);
            acc[r] += xv.x*a.x + xv.y*a.y + xv.z*a.z + xv.w*a.w;
            float4 av = *(const float4*)(Av + r*Dv + off);
            acc[8+r] += xv.x*av.x + xv.y*av.y + xv.z*av.z + xv.w*av.w;
        }
    }
    #pragma unroll
    for (int j = 0; j < 16; j++) {
        #pragma unroll
        for (int o = 16; o > 0; o >>= 1)
            acc[j] += __shfl_xor_sync(0xffffffffu, acc[j], o);
    }
    if (lane == 0) {
        float4 a0 = {acc[0], acc[1], acc[2], acc[3]};
        float4 a1 = {acc[4], acc[5], acc[6], acc[7]};
        float4 v0 = {acc[8], acc[9], acc[10], acc[11]};
        float4 v1 = {acc[12], acc[13], acc[14], acc[15]};
        *(float4*)(g_xak + m*RKv)     = a0;
        *(float4*)(g_xak + m*RKv + 4) = a1;
        *(float4*)(g_xav + m*RKv)     = v0;
        *(float4*)(g_xav + m*RKv + 4) = v1;
    }
}

// ---------------- fp16 GEMM: cp.async 3-stage pipeline ----------------
#define KC 32
#define AP 40
#define BP 136
#define A_STG (128*AP)
#define B_STG (32*BP)
#define STG_H (A_STG + B_STG)
#define STAGES 3
#define GEMM_SMEM (STG_H*STAGES*2)

// ---------------- 5) fused QKV GEMM (batch-sliced via mt0) ----------------
__global__ void __launch_bounds__(256) mma_qkv(
    const float* __restrict__ bq, const float* __restrict__ bk, const float* __restrict__ bv,
    int mt0)
{
    extern __shared__ __half hsm[];
    const uint32_t sb = cvta_smem(hsm);
    const int sel = blockIdx.x >> 3;
    const int ncol = (blockIdx.x & 7) * 128;
    const __half* W   = g_wh + (long)sel*Dv*Dv;
    const float* bias = sel == 0 ? bq : sel == 1 ? bk : bv;
    __half* Dst       = sel == 0 ? g_qf : sel == 1 ? g_kf : g_vf;

    const int tid = threadIdx.x;
    const int wid = tid >> 5, lane = tid & 31;
    const int tile_m = (mt0 + blockIdx.y) * 128;
    const int wm = (wid >> 2) * 64;
    const int wn = (wid & 3) * 32;
    const int r  = lane >> 2;
    const int qd = lane & 3;
    const int lane15 = lane & 15;
    const int colSel = (lane >> 4) << 3;

    auto issue = [&](int c, int st) {
        const long k0 = (long)c*KC;
        const uint32_t aB = sb + st*(STG_H*2);
        const uint32_t bB = aB + A_STG*2;
        #pragma unroll
        for (int e = 0; e < 2; e++) {
            int id = tid + e*256;
            int ar = id >> 2, aq = id & 3;
            CP16(aB + ar*(AP*2) + aq*16,
                 (const void*)(g_xh + (long)(tile_m + ar)*Dv + k0 + aq*8));
            int br = id >> 4, bs2 = id & 15;
            CP16(bB + br*(BP*2) + bs2*16,
                 (const void*)(W + (k0 + br)*Dv + ncol + bs2*8));
        }
    };

    float acc[4][4][4];
    #pragma unroll
    for (int mi = 0; mi < 4; mi++)
        #pragma unroll
        for (int ni = 0; ni < 4; ni++)
            #pragma unroll
            for (int t = 0; t < 4; t++) acc[mi][ni][t] = 0.f;

    issue(0, 0); CP_COMMIT();
    issue(1, 1); CP_COMMIT();
    CP_WAIT1();
    __syncthreads();

    const int NCk = Dv / KC;
    for (int c = 0; c < NCk; c++) {
        const int st = c % STAGES;
        const uint32_t aBase = sb + st*(STG_H*2);
        const uint32_t bBase = aBase + A_STG*2;
        #pragma unroll
        for (int kk = 0; kk < 2; kk++) {
            uint32_t af[4][4];
            #pragma unroll
            for (int mi = 0; mi < 4; mi++)
                LDSM_X4(af[mi][0], af[mi][1], af[mi][2], af[mi][3],
                        aBase + (wm + mi*16 + lane15)*(AP*2) + (kk*16 + colSel)*2);
            uint32_t bf[2][4];
            #pragma unroll
            for (int ni2 = 0; ni2 < 2; ni2++)
                LDSM_X4T(bf[ni2][0], bf[ni2][1], bf[ni2][2], bf[ni2][3],
                         bBase + (kk*16 + lane15)*(BP*2) + (wn + ni2*16 + colSel)*2);
            #pragma unroll
            for (int mi = 0; mi < 4; mi++)
                #pragma unroll
                for (int ni = 0; ni < 4; ni++)
                    MMA_F16(acc[mi][ni], af[mi][0], af[mi][1], af[mi][2], af[mi][3],
                            bf[ni>>1][(ni&1)*2], bf[ni>>1][(ni&1)*2 + 1]);
        }
        if (c + 2 < NCk) issue(c + 2, (c + 2) % STAGES);
        CP_COMMIT();
        CP_WAIT1();
        __syncthreads();
    }

    #pragma unroll
    for (int mi = 0; mi < 4; mi++) {
        const int row0 = tile_m + wm + mi*16 + r;
        const int b0 = row0 >> 11, s0 = row0 & 2047;
        #pragma unroll
        for (int ni = 0; ni < 4; ni++) {
            const int col = ncol + wn + ni*8 + 2*qd;
            const float bx = __ldg(bias + col), by = __ldg(bias + col + 1);
            long d0 = ((long)(b0*Hv + (col >> 6))*Sv + s0)*HDv + (col & 63);
            *(__half2*)(Dst + d0)         = __floats2half2_rn(acc[mi][ni][0] + bx, acc[mi][ni][1] + by);
            *(__half2*)(Dst + d0 + 8*HDv) = __floats2half2_rn(acc[mi][ni][2] + bx, acc[mi][ni][3] + by);
        }
    }
}

// ---------------- 6) output projection GEMM (m-sliced via mt0) ----------------
__global__ void __launch_bounds__(256) mma_out(
    const float* __restrict__ bias, float* __restrict__ C, int mt0)
{
    extern __shared__ __half hsm[];
    const uint32_t sb = cvta_smem(hsm);
    const __half* W = g_wh + 3L*Dv*Dv;
    const int tid = threadIdx.x;
    const int wid = tid >> 5, lane = tid & 31;
    const int tile_m = (mt0 + blockIdx.y) * 128;
    const int tile_n = blockIdx.x * 128;
    const int wm = (wid >> 2) * 64;
    const int wn = (wid & 3) * 32;
    const int r  = lane >> 2;
    const int qd = lane & 3;
    const int lane15 = lane & 15;
    const int colSel = (lane >> 4) << 3;

    auto issue = [&](int c, int st) {
        const long k0 = (long)c*KC;
        const uint32_t aB = sb + st*(STG_H*2);
        const uint32_t bB = aB + A_STG*2;
        #pragma unroll
        for (int e = 0; e < 2; e++) {
            int id = tid + e*256;
            int ar = id >> 2, aq = id & 3;
            CP16(aB + ar*(AP*2) + aq*16,
                 (const void*)(g_attnh + (long)(tile_m + ar)*Dv + k0 + aq*8));
            int br = id >> 4, bs2 = id & 15;
            CP16(bB + br*(BP*2) + bs2*16,
                 (const void*)(W + (k0 + br)*Dv + tile_n + bs2*8));
        }
    };

    float acc[4][4][4];
    #pragma unroll
    for (int mi = 0; mi < 4; mi++)
        #pragma unroll
        for (int ni = 0; ni < 4; ni++)
            #pragma unroll
            for (int t = 0; t < 4; t++) acc[mi][ni][t] = 0.f;

    issue(0, 0); CP_COMMIT();
    issue(1, 1); CP_COMMIT();
    CP_WAIT1();
    __syncthreads();

    const int NCk = Dv / KC;
    for (int c = 0; c < NCk; c++) {
        const int st = c % STAGES;
        const uint32_t aBase = sb + st*(STG_H*2);
        const uint32_t bBase = aBase + A_STG*2;
        #pragma unroll
        for (int kk = 0; kk < 2; kk++) {
            uint32_t af[4][4];
            #pragma unroll
            for (int mi = 0; mi < 4; mi++)
                LDSM_X4(af[mi][0], af[mi][1], af[mi][2], af[mi][3],
                        aBase + (wm + mi*16 + lane15)*(AP*2) + (kk*16 + colSel)*2);
            uint32_t bf[2][4];
            #pragma unroll
            for (int ni2 = 0; ni2 < 2; ni2++)
                LDSM_X4T(bf[ni2][0], bf[ni2][1], bf[ni2][2], bf[ni2][3],
                         bBase + (kk*16 + lane15)*(BP*2) + (wn + ni2*16 + colSel)*2);
            #pragma unroll
            for (int mi = 0; mi < 4; mi++)
                #pragma unroll
                for (int ni = 0; ni < 4; ni++)
                    MMA_F16(acc[mi][ni], af[mi][0], af[mi][1], af[mi][2], af[mi][3],
                            bf[ni>>1][(ni&1)*2], bf[ni>>1][(ni&1)*2 + 1]);
        }
        if (c + 2 < NCk) issue(c + 2, (c + 2) % STAGES);
        CP_COMMIT();
        CP_WAIT1();
        __syncthreads();
    }

    #pragma unroll
    for (int mi = 0; mi < 4; mi++) {
        const int row0 = tile_m + wm + mi*16 + r;
        #pragma unroll
        for (int ni = 0; ni < 4; ni++) {
            const int col = tile_n + wn + ni*8 + 2*qd;
            const float bx = __ldg(bias + col), by = __ldg(bias + col + 1);
            float2 v0, v1;
            v0.x = acc[mi][ni][0] + bx; v0.y = acc[mi][ni][1] + by;
            v1.x = acc[mi][ni][2] + bx; v1.y = acc[mi][ni][3] + by;
            *(float2*)(C + (long)row0*Dv + col)     = v0;
            *(float2*)(C + (long)(row0+8)*Dv + col) = v1;
        }
    }
}

// ---------------- 7) rope + dyn correction (single batch) ----------------
__device__ __forceinline__ float dot8(const float* a, const float* bp) {
    float4 a0 = *(const float4*)a,  a1 = *(const float4*)(a + 4);
    float4 b0 = *(const float4*)bp, b1 = *(const float4*)(bp + 4);
    return a0.x*b0.x + a0.y*b0.y + a0.z*b0.z + a0.w*b0.w
         + a1.x*b1.x + a1.y*b1.y + a1.z*b1.z + a1.w*b1.w;
}

__global__ void rope_dyn(int b) {
    int idx = blockIdx.x*256 + threadIdx.x;
    int d2 = idx & 31;
    int s  = (idx >> 5) & 2047;
    int h  = (idx >> 16) & 15;
    long base = ((long)((b*Hv + h)*Sv + s))*HDv;
    int m = b*Sv + s;
    const float* xak = g_xak + (long)m*RKv;
    const float* xav = g_xav + (long)m*RKv;
    const float* Bmk = g_Bm + (long)b*(Dv*RKv);
    const float* Bmv = g_Bm + (long)(Bv + b)*(Dv*RKv);
    int c0 = h*HDv + d2;
    float dk0 = 0.125f * dot8(xak, Bmk + c0*RKv);
    float dk1 = 0.125f * dot8(xak, Bmk + (c0+32)*RKv);
    float dv0 = 0.125f * dot8(xav, Bmv + c0*RKv);
    float dv1 = 0.125f * dot8(xav, Bmv + (c0+32)*RKv);

    float2 t = g_rope[(s << 5) | d2];
    float cs = t.x, sn = t.y;

    float q0 = __half2float(g_qf[base + d2]), q1 = __half2float(g_qf[base + d2 + 32]);
    g_q16[base + d2]      = __float2half(q0*cs - q1*sn);
    g_q16[base + d2 + 32] = __float2half(q1*cs + q0*sn);
    float k0 = __half2float(g_kf[base + d2]) + dk0;
    float k1 = __half2float(g_kf[base + d2 + 32]) + dk1;
    g_k16[base + d2]      = __float2half(k0*cs - k1*sn);
    g_k16[base + d2 + 32] = __float2half(k1*cs + k0*sn);
    g_v16[base + d2]      = __float2half(__half2float(g_vf[base + d2]) + dv0);
    g_v16[base + d2 + 32] = __float2half(__half2float(g_vf[base + d2 + 32]) + dv1);
}

// ---------------- 8) causal flash attention (batch-sliced via bh0) ----------------
#define FQP 72
#define FKP 72
#define KTILE_B (64*FKP*2)
#define KVSTR   (2*KTILE_B)
#define FLASH_SMEM (64*FQP*2 + 2*KVSTR)
#define FSCL 0.18033688011112042f

__global__ void __launch_bounds__(128) flash_mma(int bh0)
{
    extern __shared__ __half hsm[];
    __half* Qs = hsm;
    const uint32_t qBase  = cvta_smem(Qs);
    const uint32_t kv0Base = qBase + 64*FQP*2;

    const int qt = 31 - blockIdx.x;
    const int bh = bh0 + blockIdx.y;
    const int tid = threadIdx.x;
    const int warp = tid >> 5, lane = tid & 31;
    const int g = lane >> 2, tig = lane & 3;
    const int r0 = warp*16 + g;
    const int lane15 = lane & 15;
    const int colSel = (lane >> 4) << 3;
    const int krow_off = (lane & 7) + ((lane >> 4) & 1)*8;
    const int kcol_off = ((lane >> 3) & 1)*8;
    const int vrow_off = (lane & 7) + ((lane >> 3) & 1)*8;
    const int vcol_off = ((lane >> 4) & 1)*8;

    const __half* Qb = g_q16 + ((long)bh*Sv + qt*64)*HDv;
    const __half* Kb = g_k16 + (long)bh*Sv*HDv;
    const __half* Vb = g_v16 + (long)bh*Sv*HDv;

    const int lrow = tid >> 4;
    const int lcol = (tid & 15) * 4;

    #pragma unroll
    for (int it = 0; it < 8; it++) {
        int rr = lrow + it*8;
        *(uint2*)(Qs + rr*FQP + lcol) = *(const uint2*)(Qb + rr*HDv + lcol);
    }
    __syncthreads();
    uint32_t qf[4][4];
    #pragma unroll
    for (int kk = 0; kk < 4; kk++)
        LDSM_X4(qf[kk][0], qf[kk][1], qf[kk][2], qf[kk][3],
                qBase + (warp*16 + lane15)*(FQP*2) + (kk*16 + colSel)*2);

    float oa[8][4];
    #pragma unroll
    for (int nt = 0; nt < 8; nt++)
        #pragma unroll
        for (int e = 0; e < 4; e++) oa[nt][e] = 0.f;
    float m0 = -1e30f, m1 = -1e30f, l0 = 0.f, l1 = 0.f;

    uint2 kR[8], vR[8];
    #pragma unroll
    for (int it = 0; it < 8; it++) {
        int rr = lrow + it*8;
        kR[it] = *(const uint2*)(Kb + ((long)rr)*HDv + lcol);
        vR[it] = *(const uint2*)(Vb + ((long)rr)*HDv + lcol);
    }

    for (int jt = 0; jt <= qt; jt++) {
        const uint32_t kB = kv0Base + (jt & 1)*KVSTR;
        const uint32_t vB = kB + KTILE_B;
        __half* KsW = (__half*)(hsm + (kB - qBase)/2);
        __half* VsW = KsW + 64*FKP;
        #pragma unroll
        for (int it = 0; it < 8; it++) {
            int rr = lrow + it*8;
            *(uint2*)(KsW + rr*FKP + lcol) = kR[it];
            *(uint2*)(VsW + rr*FKP + lcol) = vR[it];
        }
        __syncthreads();
        if (jt < qt) {
            #pragma unroll
            for (int it = 0; it < 8; it++) {
                int rr = (jt + 1)*64 + lrow + it*8;
                kR[it] = *(const uint2*)(Kb + ((long)rr)*HDv + lcol);
                vR[it] = *(const uint2*)(Vb + ((long)rr)*HDv + lcol);
            }
        }

        float s[8][4];
        #pragma unroll
        for (int nt = 0; nt < 8; nt++)
            #pragma unroll
            for (int e = 0; e < 4; e++) s[nt][e] = 0.f;
        #pragma unroll
        for (int ni2 = 0; ni2 < 4; ni2++) {
            #pragma unroll
            for (int kk = 0; kk < 4; kk++) {
                uint32_t kf0, kf1, kf2, kf3;
                LDSM_X4(kf0, kf1, kf2, kf3,
                        kB + (ni2*16 + krow_off)*(FKP*2) + (kk*16 + kcol_off)*2);
                MMA_F16(s[2*ni2],   qf[kk][0], qf[kk][1], qf[kk][2], qf[kk][3], kf0, kf1);
                MMA_F16(s[2*ni2+1], qf[kk][0], qf[kk][1], qf[kk][2], qf[kk][3], kf2, kf3);
            }
        }

        #pragma unroll
        for (int nt = 0; nt < 8; nt++) {
            #pragma unroll
            for (int e = 0; e < 4; e++) s[nt][e] *= FSCL;
            if (jt == qt) {
                int c0 = nt*8 + 2*tig;
                if (c0     > r0)     s[nt][0] = -1e30f;
                if (c0 + 1 > r0)     s[nt][1] = -1e30f;
                if (c0     > r0 + 8) s[nt][2] = -1e30f;
                if (c0 + 1 > r0 + 8) s[nt][3] = -1e30f;
            }
        }

        float mx0 = -1e30f, mx1 = -1e30f;
        #pragma unroll
        for (int nt = 0; nt < 8; nt++) {
            mx0 = fmaxf(mx0, fmaxf(s[nt][0], s[nt][1]));
            mx1 = fmaxf(mx1, fmaxf(s[nt][2], s[nt][3]));
        }
        mx0 = fmaxf(mx0, __shfl_xor_sync(0xffffffffu, mx0, 1));
        mx0 = fmaxf(mx0, __shfl_xor_sync(0xffffffffu, mx0, 2));
        mx1 = fmaxf(mx1, __shfl_xor_sync(0xffffffffu, mx1, 1));
        mx1 = fmaxf(mx1, __shfl_xor_sync(0xffffffffu, mx1, 2));
        float mn0 = fmaxf(m0, mx0), mn1 = fmaxf(m1, mx1);
        float al0 = ex2(m0 - mn0), al1 = ex2(m1 - mn1);
        m0 = mn0; m1 = mn1;

        uint32_t ph0[8], ph1[8];
        float ls0 = 0.f, ls1 = 0.f;
        #pragma unroll
        for (int nt = 0; nt < 8; nt++) {
            ph0[nt] = ex2h2(s[nt][0] - m0, s[nt][1] - m0);
            ph1[nt] = ex2h2(s[nt][2] - m1, s[nt][3] - m1);
            float2 fa = __half22float2(*(__half2*)&ph0[nt]);
            float2 fb = __half22float2(*(__half2*)&ph1[nt]);
            ls0 += fa.x + fa.y;
            ls1 += fb.x + fb.y;
        }
        ls0 += __shfl_xor_sync(0xffffffffu, ls0, 1);
        ls0 += __shfl_xor_sync(0xffffffffu, ls0, 2);
        ls1 += __shfl_xor_sync(0xffffffffu, ls1, 1);
        ls1 += __shfl_xor_sync(0xffffffffu, ls1, 2);
        l0 = l0*al0 + ls0;
        l1 = l1*al1 + ls1;
        #pragma unroll
        for (int nt = 0; nt < 8; nt++) {
            oa[nt][0] *= al0; oa[nt][1] *= al0;
            oa[nt][2] *= al1; oa[nt][3] *= al1;
        }

        #pragma unroll
        for (int kt = 0; kt < 4; kt++) {
            uint32_t pa0 = ph0[2*kt];
            uint32_t pa1 = ph1[2*kt];
            uint32_t pa2 = ph0[2*kt+1];
            uint32_t pa3 = ph1[2*kt+1];
            #pragma unroll
            for (int g16 = 0; g16 < 4; g16++) {
                uint32_t vf0, vf1, vf2, vf3;
                LDSM_X4T(vf0, vf1, vf2, vf3,
                         vB + (kt*16 + vrow_off)*(FKP*2) + (g16*16 + vcol_off)*2);
                MMA_F16(oa[2*g16],   pa0, pa1, pa2, pa3, vf0, vf1);
                MMA_F16(oa[2*g16+1], pa0, pa1, pa2, pa3, vf2, vf3);
            }
        }
    }

    const int b = bh >> 4, h = bh & 15;
    const float inv0 = 1.f / l0, inv1 = 1.f / l1;
    const int rg0 = qt*64 + r0;
    #pragma unroll
    for (int nt = 0; nt < 8; nt++) {
        int col = h*HDv + nt*8 + 2*tig;
        __half2* o0 = (__half2*)(g_attnh + ((long)(b*Sv + rg0))*Dv + col);
        __half2* o1 = (__half2*)(g_attnh + ((long)(b*Sv + rg0 + 8))*Dv + col);
        *o0 = __floats2half2_rn(oa[nt][0]*inv0, oa[nt][1]*inv0);
        *o1 = __floats2half2_rn(oa[nt][2]*inv1, oa[nt][3]*inv1);
    }
}

// ---------------- launch: R14 topology + shortened prologue ----------------
extern "C" void kernel_launch(void* const* d_in, const int* in_sizes, int n_in,
                              void* d_out, int out_size) {
    const float* x      = (const float*)d_in[0];
    const float* Wq     = (const float*)d_in[1];
    const float* bq     = (const float*)d_in[2];
    const float* Wo     = (const float*)d_in[3];
    const float* bo     = (const float*)d_in[4];
    const float* Wk     = (const float*)d_in[5];
    const float* bk     = (const float*)d_in[6];
    const float* k_w1   = (const float*)d_in[7];
    const float* k_b1   = (const float*)d_in[8];
    const float* k_w2   = (const float*)d_in[9];
    const float* k_b2   = (const float*)d_in[10];
    const float* k_gA_w = (const float*)d_in[11];
    const float* k_gA_b = (const float*)d_in[12];
    const float* k_gB_w = (const float*)d_in[13];
    const float* k_gB_b = (const float*)d_in[14];
    const float* Wv     = (const float*)d_in[15];
    const float* bv     = (const float*)d_in[16];
    const float* v_w1   = (const float*)d_in[17];
    const float* v_b1   = (const float*)d_in[18];
    const float* v_w2   = (const float*)d_in[19];
    const float* v_b2   = (const float*)d_in[20];
    const float* v_gA_w = (const float*)d_in[21];
    const float* v_gA_b = (const float*)d_in[22];
    const float* v_gB_w = (const float*)d_in[23];
    const float* v_gB_b = (const float*)d_in[24];
    float* out = (float*)d_out;

    cudaFuncSetAttribute(flash_mma, cudaFuncAttributeMaxDynamicSharedMemorySize, FLASH_SMEM);
    cudaFuncSetAttribute(mma_qkv, cudaFuncAttributeMaxDynamicSharedMemorySize, GEMM_SMEM);
    cudaFuncSetAttribute(mma_out, cudaFuncAttributeMaxDynamicSharedMemorySize, GEMM_SMEM);

    static cudaStream_t s1 = nullptr, s2 = nullptr;
    static cudaEvent_t evFork = nullptr, evP = nullptr, evQ0 = nullptr, evT = nullptr, evJ2 = nullptr;
    if (s1 == nullptr) {
        cudaStreamCreateWithFlags(&s1, cudaStreamNonBlocking);
        cudaStreamCreateWithFlags(&s2, cudaStreamNonBlocking);
        cudaEventCreateWithFlags(&evFork, cudaEventDisableTiming);
        cudaEventCreateWithFlags(&evP,    cudaEventDisableTiming);
        cudaEventCreateWithFlags(&evQ0,   cudaEventDisableTiming);
        cudaEventCreateWithFlags(&evT,    cudaEventDisableTiming);
        cudaEventCreateWithFlags(&evJ2,   cudaEventDisableTiming);
    }

    cudaEventRecord(evFork, 0);

    // s1: shortened prologue chain
    cudaStreamWaitEvent(s1, evFork, 0);
    pool_partial<<<dim3(4, 8, Bv), 256, 0, s1>>>(x);
    hyp_h<<<dim3(2, Bv, 16), 256, 0, s1>>>(k_w1, v_w1);
    hyp_c<<<dim3(2, Bv, 4), 256, 0, s1>>>(k_w2, k_b2, v_w2, v_b2, k_b1, v_b1);
    hyp_AB<<<dim3(2, Bv, 64), 256, 0, s1>>>(k_gA_w, k_gA_b, k_gB_w, k_gB_b,
                                            v_gA_w, v_gA_b, v_gB_w, v_gB_b);
    xa_kernel<<<512, 256, 0, s1>>>(x);
    cudaEventRecord(evP, s1);

    // s2 head: rope table (off the s1 critical chain)
    cudaStreamWaitEvent(s2, evFork, 0);
    rope_table<<<256, 256, 0, s2>>>();
    cudaEventRecord(evT, s2);

    // main: cvt_w -> cvt_x -> qkv b0 -> qkv b1
    cvt_w<<<dim3(1024, 4), 256>>>(Wq, Wk, Wv, Wo);
    cvt_x<<<dim3(1024, 4), 256>>>(x);
    mma_qkv<<<dim3(24, 16), 256, GEMM_SMEM>>>(bq, bk, bv, 0);
    cudaEventRecord(evQ0, 0);
    mma_qkv<<<dim3(24, 16), 256, GEMM_SMEM>>>(bq, bk, bv, 16);

    // s2: batch-0 tail pipeline (overlaps qkv b1 / flash b1)
    cudaStreamWaitEvent(s2, evQ0, 0);
    cudaStreamWaitEvent(s2, evP, 0);
    rope_dyn<<<4096, 256, 0, s2>>>(0);
    flash_mma<<<dim3(32, 16), 128, FLASH_SMEM, s2>>>(0);
    mma_out<<<dim3(8, 16), 256, GEMM_SMEM, s2>>>(bo, out, 0);
    cudaEventRecord(evJ2, s2);

    // main: batch-1 tail pipeline
    cudaStreamWaitEvent(0, evP, 0);
    cudaStreamWaitEvent(0, evT, 0);
    rope_dyn<<<4096, 256>>>(1);
    flash_mma<<<dim3(32, 16), 128, FLASH_SMEM>>>(16);
    mma_out<<<dim3(8, 16), 256, GEMM_SMEM>>>(bo, out, 16);
    cudaStreamWaitEvent(0, evJ2, 0);
}